// round 16
// baseline (speedup 1.0000x reference)
#include <cuda_runtime.h>
#include <math.h>

#define WS_      14
#define NTOK     196
#define NH_      12
#define HD_      64
#define DIM_     768
#define NWIN     200
#define BH_      2400
#define MROWS    39200
#define IMGHW    64
#define QKV_N    2304

// ---- scratch ----
__device__ float g_q   [BH_ * NTOK * HD_];
__device__ float g_k   [BH_ * NTOK * HD_];
__device__ float g_v   [BH_ * NTOK * HD_];
__device__ float g_ao  [MROWS * DIM_];

// ---- packed f32x2 helpers ----
__device__ __forceinline__ unsigned long long pk2(float x, float y) {
    unsigned long long r;
    asm("mov.b64 %0, {%1, %2};" : "=l"(r) : "f"(x), "f"(y));
    return r;
}
__device__ __forceinline__ void upk2(unsigned long long v, float& x, float& y) {
    asm("mov.b64 {%0, %1}, %2;" : "=f"(x), "=f"(y) : "l"(v));
}
#define FFMA2(C, A, B) \
    asm("fma.rn.f32x2 %0, %1, %2, %0;" : "+l"(C) : "l"(A), "l"(B))

// =====================================================================
// GEMM 1: qkv (round-15 passing version, f32x2)
// =====================================================================
__global__ __launch_bounds__(256)
void qkv_gemm(const float* __restrict__ x, const float* __restrict__ w,
              const float* __restrict__ bias)
{
    __shared__ float As[2][16][132];
    __shared__ float Bs[2][16][132];
    const int tid = threadIdx.x;
    const int m0 = blockIdx.x * 128;
    const int n0 = blockIdx.y * 128;
    const int tx = tid & 15;
    const int ty = tid >> 4;

    int abase[2];
#pragma unroll
    for (int i = 0; i < 2; i++) {
        int lin = tid + 256 * i;
        int row = lin >> 2;
        int gm  = m0 + row;
        int base = -1;
        if (gm < MROWS) {
            int wdw = gm / NTOK, t = gm - wdw * NTOK;
            int b  = wdw / 25,  wi = wdw - b * 25;
            int wh = wi / 5,    ww = wi - wh * 5;
            int th = t / WS_,   tw = t - th * WS_;
            int y  = wh * WS_ + th;
            int xc = ww * WS_ + tw;
            if (y < IMGHW && xc < IMGHW)
                base = ((b * IMGHW + y) * IMGHW + xc) * DIM_;
        }
        abase[i] = base;
    }

    unsigned long long acc[8][4];
#pragma unroll
    for (int i = 0; i < 8; i++)
#pragma unroll
        for (int j = 0; j < 4; j++) acc[i][j] = 0ULL;

    float4 pa[2], pb[2];
#pragma unroll
    for (int i = 0; i < 2; i++) {
        int lin = tid + 256 * i;
        int kq  = (lin & 3) * 4;
        pa[i] = make_float4(0.f, 0.f, 0.f, 0.f);
        if (abase[i] >= 0) pa[i] = *(const float4*)(x + abase[i] + kq);
        int row = lin >> 2;
        pb[i] = *(const float4*)(w + (n0 + row) * DIM_ + kq);
    }
#pragma unroll
    for (int i = 0; i < 2; i++) {
        int lin = tid + 256 * i;
        int row = lin >> 2;
        int kq  = (lin & 3) * 4;
        As[0][kq + 0][row] = pa[i].x; As[0][kq + 1][row] = pa[i].y;
        As[0][kq + 2][row] = pa[i].z; As[0][kq + 3][row] = pa[i].w;
        Bs[0][kq + 0][row] = pb[i].x; Bs[0][kq + 1][row] = pb[i].y;
        Bs[0][kq + 2][row] = pb[i].z; Bs[0][kq + 3][row] = pb[i].w;
    }
    __syncthreads();

    const int NK = DIM_ / 16;
    for (int c = 0; c < NK; c++) {
        if (c + 1 < NK) {
            int k0 = (c + 1) * 16;
#pragma unroll
            for (int i = 0; i < 2; i++) {
                int lin = tid + 256 * i;
                int kq  = (lin & 3) * 4;
                pa[i] = make_float4(0.f, 0.f, 0.f, 0.f);
                if (abase[i] >= 0) pa[i] = *(const float4*)(x + abase[i] + k0 + kq);
                int row = lin >> 2;
                pb[i] = *(const float4*)(w + (n0 + row) * DIM_ + k0 + kq);
            }
        }
        const int buf = c & 1;
#pragma unroll
        for (int kk = 0; kk < 16; kk++) {
            float4 t0 = *(const float4*)&As[buf][kk][ty * 8];
            float4 t1 = *(const float4*)&As[buf][kk][ty * 8 + 4];
            float4 u0 = *(const float4*)&Bs[buf][kk][tx * 8];
            float4 u1 = *(const float4*)&Bs[buf][kk][tx * 8 + 4];
            unsigned long long a2[8], b2[4];
            a2[0]=pk2(t0.x,t0.x); a2[1]=pk2(t0.y,t0.y);
            a2[2]=pk2(t0.z,t0.z); a2[3]=pk2(t0.w,t0.w);
            a2[4]=pk2(t1.x,t1.x); a2[5]=pk2(t1.y,t1.y);
            a2[6]=pk2(t1.z,t1.z); a2[7]=pk2(t1.w,t1.w);
            b2[0]=pk2(u0.x,u0.y); b2[1]=pk2(u0.z,u0.w);
            b2[2]=pk2(u1.x,u1.y); b2[3]=pk2(u1.z,u1.w);
#pragma unroll
            for (int i = 0; i < 8; i++)
#pragma unroll
                for (int j = 0; j < 4; j++)
                    FFMA2(acc[i][j], a2[i], b2[j]);
        }
        if (c + 1 < NK) {
            const int nb = (c + 1) & 1;
#pragma unroll
            for (int i = 0; i < 2; i++) {
                int lin = tid + 256 * i;
                int row = lin >> 2;
                int kq  = (lin & 3) * 4;
                As[nb][kq + 0][row] = pa[i].x; As[nb][kq + 1][row] = pa[i].y;
                As[nb][kq + 2][row] = pa[i].z; As[nb][kq + 3][row] = pa[i].w;
                Bs[nb][kq + 0][row] = pb[i].x; Bs[nb][kq + 1][row] = pb[i].y;
                Bs[nb][kq + 2][row] = pb[i].z; Bs[nb][kq + 3][row] = pb[i].w;
            }
        }
        __syncthreads();
    }

#pragma unroll
    for (int i = 0; i < 8; i++) {
        int gm = m0 + ty * 8 + i;
        if (gm >= MROWS) continue;
        int wdw = gm / NTOK, t = gm - wdw * NTOK;
#pragma unroll
        for (int jp = 0; jp < 4; jp++) {
            float v0, v1;
            upk2(acc[i][jp], v0, v1);
#pragma unroll
            for (int e = 0; e < 2; e++) {
                int gn = n0 + tx * 8 + jp * 2 + e;
                float cv = (e ? v1 : v0) + bias[gn];
                int which = gn / DIM_;
                int r = gn - which * DIM_;
                int h = r >> 6, d = r & 63;
                int idx = ((wdw * NH_ + h) * NTOK + t) * HD_ + d;
                float* dst = (which == 0) ? g_q : ((which == 1) ? g_k : g_v);
                dst[idx] = cv;
            }
        }
    }
}

// =====================================================================
// fused attention: scores(+rel) -> softmax -> AV, all in one CTA.
// grid (2, BH_), block 256, smem 204 KB (1 CTA/SM).
// layout (floats): As[8448] Bs[8448] Th[3712] Tw[3712] S[128*209]
//   V (208x68 = 14144) later overwrites As+Bs (16896).
// =====================================================================
#define SSTR 209
#define FA_SMEM_FLOATS (8448 + 8448 + 3712 + 3712 + 128 * SSTR)
#define FA_SMEM_BYTES  (FA_SMEM_FLOATS * 4)
#define NREL 27

__global__ __launch_bounds__(256)
void fused_attn(const float* __restrict__ rph, const float* __restrict__ rpw)
{
    extern __shared__ float sm[];
    float* As  = sm;               // [64][132]
    float* Bs  = sm + 8448;        // [64][132]; tables staged here first
    float* Th  = sm + 16896;       // [128][29]
    float* Tw  = sm + 20608;       // [128][29]
    float* S   = sm + 24320;       // [128][209]
    float* tbl = Bs;
    float* Vs  = sm;               // [208][68] reuses As+Bs after softmax

    const int tid = threadIdx.x;
    const int bh  = blockIdx.y;
    const int m0  = blockIdx.x * 128;
    const int tx  = tid & 15;
    const int ty  = tid >> 4;
    const float* Q = g_q + bh * (NTOK * HD_);
    const float* K = g_k + bh * (NTOK * HD_);
    const float* V = g_v + bh * (NTOK * HD_);
    const int wdw = bh / NH_, hh = bh - wdw * NH_;

    // ---- stage Q transposed + rel tables ----
#pragma unroll
    for (int i = 0; i < 8; i++) {
        int e = tid + 256 * i;
        int row = e >> 4;
        int d0  = (e & 15) * 4;
        float4 v = make_float4(0.f, 0.f, 0.f, 0.f);
        if (m0 + row < NTOK) v = *(const float4*)(Q + (m0 + row) * HD_ + d0);
        As[(d0 + 0) * 132 + row] = v.x;
        As[(d0 + 1) * 132 + row] = v.y;
        As[(d0 + 2) * 132 + row] = v.z;
        As[(d0 + 3) * 132 + row] = v.w;
    }
    for (int i = tid; i < 2 * NREL * HD_; i += 256) {
        int isW = (i >= NREL * HD_);
        int l = isW ? i - NREL * HD_ : i;
        int r = l >> 6, d = l & 63;
        tbl[(isW ? 1755 : 0) + r * 65 + d] = __ldg((isW ? rpw : rph) + r * HD_ + d);
    }
    __syncthreads();

    // ---- Th/Tw = Q_tile @ table^T ----
    {
        const int ty2 = tid >> 3;
        const int tx2 = tid & 7;
#pragma unroll
        for (int tb = 0; tb < 2; tb++) {
            const float* tb_base = tbl + (tb ? 1755 : 0);
            float* Tout = tb ? Tw : Th;
            float t[4][4];
#pragma unroll
            for (int i = 0; i < 4; i++)
#pragma unroll
                for (int j = 0; j < 4; j++) t[i][j] = 0.f;
#pragma unroll 8
            for (int d = 0; d < HD_; d++) {
                float qv[4], tv[4];
#pragma unroll
                for (int i = 0; i < 4; i++)
                    qv[i] = As[d * 132 + ty2 * 4 + i];
#pragma unroll
                for (int j = 0; j < 4; j++) {
                    int col = tx2 * 4 + j;
                    tv[j] = tb_base[(col < NREL ? col : 0) * 65 + d];
                }
#pragma unroll
                for (int i = 0; i < 4; i++)
#pragma unroll
                    for (int j = 0; j < 4; j++)
                        t[i][j] = fmaf(qv[i], tv[j], t[i][j]);
            }
#pragma unroll
            for (int j = 0; j < 4; j++) {
                int col = tx2 * 4 + j;
                if (col < NREL) {
#pragma unroll
                    for (int i = 0; i < 4; i++)
                        Tout[(ty2 * 4 + i) * 29 + col] = t[i][j];
                }
            }
        }
    }
    __syncthreads();

    // ---- scores: two K halves, S kept in smem ----
    for (int half = 0; half < 2; half++) {
        const int n0 = half * 128;
#pragma unroll
        for (int i = 0; i < 8; i++) {
            int e = tid + 256 * i;
            int row = e >> 4;
            int d0  = (e & 15) * 4;
            float4 v = make_float4(0.f, 0.f, 0.f, 0.f);
            if (n0 + row < NTOK) v = *(const float4*)(K + (n0 + row) * HD_ + d0);
            Bs[(d0 + 0) * 132 + row] = v.x;
            Bs[(d0 + 1) * 132 + row] = v.y;
            Bs[(d0 + 2) * 132 + row] = v.z;
            Bs[(d0 + 3) * 132 + row] = v.w;
        }
        __syncthreads();

        float acc[8][8];
#pragma unroll
        for (int i = 0; i < 8; i++)
#pragma unroll
            for (int j = 0; j < 8; j++) acc[i][j] = 0.f;

#pragma unroll 8
        for (int kk = 0; kk < HD_; kk++) {
            float a[8], b[8];
            float4 t0 = *(const float4*)&As[kk * 132 + ty * 8];
            float4 t1 = *(const float4*)&As[kk * 132 + ty * 8 + 4];
            a[0]=t0.x; a[1]=t0.y; a[2]=t0.z; a[3]=t0.w;
            a[4]=t1.x; a[5]=t1.y; a[6]=t1.z; a[7]=t1.w;
            float4 u0 = *(const float4*)&Bs[kk * 132 + tx * 8];
            float4 u1 = *(const float4*)&Bs[kk * 132 + tx * 8 + 4];
            b[0]=u0.x; b[1]=u0.y; b[2]=u0.z; b[3]=u0.w;
            b[4]=u1.x; b[5]=u1.y; b[6]=u1.z; b[7]=u1.w;
#pragma unroll
            for (int i = 0; i < 8; i++)
#pragma unroll
                for (int j = 0; j < 8; j++)
                    acc[i][j] = fmaf(a[i], b[j], acc[i][j]);
        }

        int khs[8], kws[8];
#pragma unroll
        for (int j = 0; j < 8; j++) {
            int gn = n0 + tx * 8 + j;
            int kh = gn / WS_;
            khs[j] = kh;
            kws[j] = gn - kh * WS_;
        }
#pragma unroll
        for (int i = 0; i < 8; i++) {
            int lrow = ty * 8 + i;
            int gm = m0 + lrow;
            int qh  = (gm < NTOK) ? gm / WS_ : 0;
            int qwc = (gm < NTOK) ? gm - qh * WS_ : 0;
            const float* thr = Th + lrow * 29 + (qh + WS_ - 1);
            const float* twr = Tw + lrow * 29 + (qwc + WS_ - 1);
#pragma unroll
            for (int j = 0; j < 8; j++) {
                int gn = n0 + tx * 8 + j;
                if (gn >= SSTR) continue;
                float val = -1e30f;
                if (gm < NTOK && gn < NTOK)
                    val = acc[i][j] * 0.125f + thr[-khs[j]] + twr[-kws[j]];
                S[lrow * SSTR + gn] = val;
            }
        }
        __syncthreads();
    }

    // ---- softmax in smem: warp per row ----
    {
        const int warp = tid >> 5;
        const int lane = tid & 31;
        for (int r = warp; r < 128; r += 8) {
            float* srow = S + r * SSTR;
            float v[7];
            float mx = -1e30f;
#pragma unroll
            for (int t = 0; t < 7; t++) {
                int j = lane + 32 * t;
                v[t] = (j < SSTR) ? srow[j] : -1e30f;
                mx = fmaxf(mx, v[t]);
            }
#pragma unroll
            for (int off = 16; off > 0; off >>= 1)
                mx = fmaxf(mx, __shfl_xor_sync(0xffffffffu, mx, off));
            float sum = 0.f;
#pragma unroll
            for (int t = 0; t < 7; t++) {
                int j = lane + 32 * t;
                if (j < SSTR) {
                    float e = __expf(v[t] - mx);
                    v[t] = e;
                    sum += e;
                }
            }
#pragma unroll
            for (int off = 16; off > 0; off >>= 1)
                sum += __shfl_xor_sync(0xffffffffu, sum, off);
            float inv = 1.f / sum;
#pragma unroll
            for (int t = 0; t < 7; t++) {
                int j = lane + 32 * t;
                if (j < SSTR) srow[j] = v[t] * inv;
            }
        }
    }
    __syncthreads();

    // ---- stage V over As/Bs region ----
    for (int i = tid; i < 208 * 16; i += 256) {
        int row = i >> 4;
        int c4  = (i & 15) * 4;
        float4 v = make_float4(0.f, 0.f, 0.f, 0.f);
        if (row < NTOK) v = *(const float4*)(V + row * HD_ + c4);
        *(float4*)&Vs[row * 68 + c4] = v;
    }
    __syncthreads();

    // ---- AV: S[128][209] x V[208][64] -> out[128][64] ----
    {
        const int ty2 = tid >> 3;      // rows ty2*4..+3
        const int tx2 = tid & 7;       // cols tx2*8..+7
        float acc2[4][8];
#pragma unroll
        for (int i = 0; i < 4; i++)
#pragma unroll
            for (int j = 0; j < 8; j++) acc2[i][j] = 0.f;

#pragma unroll 4
        for (int kk = 0; kk < 208; kk++) {
            float a[4], b[8];
#pragma unroll
            for (int i = 0; i < 4; i++)
                a[i] = S[(ty2 * 4 + i) * SSTR + kk];
            float4 u0 = *(const float4*)&Vs[kk * 68 + tx2 * 8];
            float4 u1 = *(const float4*)&Vs[kk * 68 + tx2 * 8 + 4];
            b[0]=u0.x; b[1]=u0.y; b[2]=u0.z; b[3]=u0.w;
            b[4]=u1.x; b[5]=u1.y; b[6]=u1.z; b[7]=u1.w;
#pragma unroll
            for (int i = 0; i < 4; i++)
#pragma unroll
                for (int j = 0; j < 8; j++)
                    acc2[i][j] = fmaf(a[i], b[j], acc2[i][j]);
        }

#pragma unroll
        for (int i = 0; i < 4; i++) {
            int gm = m0 + ty2 * 4 + i;
            if (gm >= NTOK) continue;
            float* orow = g_ao + (size_t)(wdw * NTOK + gm) * DIM_ + hh * HD_ + tx2 * 8;
            *(float4*)orow       = make_float4(acc2[i][0], acc2[i][1], acc2[i][2], acc2[i][3]);
            *(float4*)(orow + 4) = make_float4(acc2[i][4], acc2[i][5], acc2[i][6], acc2[i][7]);
        }
    }
}

// =====================================================================
// GEMM 2: proj (round-15 passing version, f32x2)
// =====================================================================
__global__ __launch_bounds__(256)
void proj_gemm(const float* __restrict__ w, const float* __restrict__ bias,
               float* __restrict__ out)
{
    __shared__ float As[2][16][132];
    __shared__ float Bs[2][16][132];
    const int tid = threadIdx.x;
    const int m0 = blockIdx.x * 128;
    const int n0 = blockIdx.y * 128;
    const int tx = tid & 15;
    const int ty = tid >> 4;

    int abase[2];
#pragma unroll
    for (int i = 0; i < 2; i++) {
        int lin = tid + 256 * i;
        int row = lin >> 2;
        int gm  = m0 + row;
        abase[i] = (gm < MROWS) ? gm * DIM_ : -1;
    }

    unsigned long long acc[8][4];
#pragma unroll
    for (int i = 0; i < 8; i++)
#pragma unroll
        for (int j = 0; j < 4; j++) acc[i][j] = 0ULL;

    float4 pa[2], pb[2];
#pragma unroll
    for (int i = 0; i < 2; i++) {
        int lin = tid + 256 * i;
        int kq  = (lin & 3) * 4;
        pa[i] = make_float4(0.f, 0.f, 0.f, 0.f);
        if (abase[i] >= 0) pa[i] = *(const float4*)(g_ao + abase[i] + kq);
        int row = lin >> 2;
        pb[i] = *(const float4*)(w + (n0 + row) * DIM_ + kq);
    }
#pragma unroll
    for (int i = 0; i < 2; i++) {
        int lin = tid + 256 * i;
        int row = lin >> 2;
        int kq  = (lin & 3) * 4;
        As[0][kq + 0][row] = pa[i].x; As[0][kq + 1][row] = pa[i].y;
        As[0][kq + 2][row] = pa[i].z; As[0][kq + 3][row] = pa[i].w;
        Bs[0][kq + 0][row] = pb[i].x; Bs[0][kq + 1][row] = pb[i].y;
        Bs[0][kq + 2][row] = pb[i].z; Bs[0][kq + 3][row] = pb[i].w;
    }
    __syncthreads();

    const int NK = DIM_ / 16;
    for (int c = 0; c < NK; c++) {
        if (c + 1 < NK) {
            int k0 = (c + 1) * 16;
#pragma unroll
            for (int i = 0; i < 2; i++) {
                int lin = tid + 256 * i;
                int kq  = (lin & 3) * 4;
                pa[i] = make_float4(0.f, 0.f, 0.f, 0.f);
                if (abase[i] >= 0) pa[i] = *(const float4*)(g_ao + abase[i] + k0 + kq);
                int row = lin >> 2;
                pb[i] = *(const float4*)(w + (n0 + row) * DIM_ + k0 + kq);
            }
        }
        const int buf = c & 1;
#pragma unroll
        for (int kk = 0; kk < 16; kk++) {
            float4 t0 = *(const float4*)&As[buf][kk][ty * 8];
            float4 t1 = *(const float4*)&As[buf][kk][ty * 8 + 4];
            float4 u0 = *(const float4*)&Bs[buf][kk][tx * 8];
            float4 u1 = *(const float4*)&Bs[buf][kk][tx * 8 + 4];
            unsigned long long a2[8], b2[4];
            a2[0]=pk2(t0.x,t0.x); a2[1]=pk2(t0.y,t0.y);
            a2[2]=pk2(t0.z,t0.z); a2[3]=pk2(t0.w,t0.w);
            a2[4]=pk2(t1.x,t1.x); a2[5]=pk2(t1.y,t1.y);
            a2[6]=pk2(t1.z,t1.z); a2[7]=pk2(t1.w,t1.w);
            b2[0]=pk2(u0.x,u0.y); b2[1]=pk2(u0.z,u0.w);
            b2[2]=pk2(u1.x,u1.y); b2[3]=pk2(u1.z,u1.w);
#pragma unroll
            for (int i = 0; i < 8; i++)
#pragma unroll
                for (int j = 0; j < 4; j++)
                    FFMA2(acc[i][j], a2[i], b2[j]);
        }
        if (c + 1 < NK) {
            const int nb = (c + 1) & 1;
#pragma unroll
            for (int i = 0; i < 2; i++) {
                int lin = tid + 256 * i;
                int row = lin >> 2;
                int kq  = (lin & 3) * 4;
                As[nb][kq + 0][row] = pa[i].x; As[nb][kq + 1][row] = pa[i].y;
                As[nb][kq + 2][row] = pa[i].z; As[nb][kq + 3][row] = pa[i].w;
                Bs[nb][kq + 0][row] = pb[i].x; Bs[nb][kq + 1][row] = pb[i].y;
                Bs[nb][kq + 2][row] = pb[i].z; Bs[nb][kq + 3][row] = pb[i].w;
            }
        }
        __syncthreads();
    }

#pragma unroll
    for (int i = 0; i < 8; i++) {
        int gm = m0 + ty * 8 + i;
        if (gm >= MROWS) continue;
        int wdw = gm / NTOK, t = gm - wdw * NTOK;
        int b  = wdw / 25,  wi = wdw - b * 25;
        int wh = wi / 5,    ww = wi - wh * 5;
        int th = t / WS_,   tw = t - th * WS_;
        int y  = wh * WS_ + th;
        int xc = ww * WS_ + tw;
        if (y >= IMGHW || xc >= IMGHW) continue;
        float* orow = out + ((b * IMGHW + y) * IMGHW + xc) * DIM_;
#pragma unroll
        for (int jp = 0; jp < 4; jp++) {
            float v0, v1;
            upk2(acc[i][jp], v0, v1);
            int gn = n0 + tx * 8 + jp * 2;
            orow[gn]     = v0 + bias[gn];
            orow[gn + 1] = v1 + bias[gn + 1];
        }
    }
}

// =====================================================================
extern "C" void kernel_launch(void* const* d_in, const int* in_sizes, int n_in,
                              void* d_out, int out_size)
{
    const float* x      = (const float*)d_in[0];
    const float* qkv_w  = (const float*)d_in[1];
    const float* qkv_b  = (const float*)d_in[2];
    const float* proj_w = (const float*)d_in[3];
    const float* proj_b = (const float*)d_in[4];
    const float* rph    = (const float*)d_in[5];
    const float* rpw    = (const float*)d_in[6];
    float* out = (float*)d_out;

    cudaFuncSetAttribute(fused_attn,
                         cudaFuncAttributeMaxDynamicSharedMemorySize, FA_SMEM_BYTES);

    dim3 g1((MROWS + 127) / 128, QKV_N / 128);
    qkv_gemm<<<g1, 256>>>(x, qkv_w, qkv_b);

    dim3 gf(2, BH_);
    fused_attn<<<gf, 256, FA_SMEM_BYTES>>>(rph, rpw);

    dim3 g2((MROWS + 127) / 128, DIM_ / 128);
    proj_gemm<<<g2, 256>>>(proj_w, proj_b, out);
}

// round 17
// speedup vs baseline: 1.0977x; 1.0977x over previous
#include <cuda_runtime.h>
#include <math.h>

#define WS_      14
#define NTOK     196
#define NH_      12
#define HD_      64
#define DIM_     768
#define NWIN     200
#define BH_      2400
#define MROWS    39200
#define IMGHW    64
#define QKV_N    2304
#define NN_      38416   // 196*196

// ---- scratch ----
__device__ float g_q   [BH_ * NTOK * HD_];
__device__ float g_k   [BH_ * NTOK * HD_];
__device__ float g_v   [BH_ * NTOK * HD_];
__device__ float g_ao  [MROWS * DIM_];
__device__ float g_s   [BH_ * NN_];

// ---- packed f32x2 helpers ----
__device__ __forceinline__ unsigned long long pk2(float x, float y) {
    unsigned long long r;
    asm("mov.b64 %0, {%1, %2};" : "=l"(r) : "f"(x), "f"(y));
    return r;
}
__device__ __forceinline__ void upk2(unsigned long long v, float& x, float& y) {
    asm("mov.b64 {%0, %1}, %2;" : "=f"(x), "=f"(y) : "l"(v));
}
#define FFMA2(C, A, B) \
    asm("fma.rn.f32x2 %0, %1, %2, %0;" : "+l"(C) : "l"(A), "l"(B))

// =====================================================================
// GEMM 1: qkv (round-15 passing version, f32x2)
// =====================================================================
__global__ __launch_bounds__(256)
void qkv_gemm(const float* __restrict__ x, const float* __restrict__ w,
              const float* __restrict__ bias)
{
    __shared__ float As[2][16][132];
    __shared__ float Bs[2][16][132];
    const int tid = threadIdx.x;
    const int m0 = blockIdx.x * 128;
    const int n0 = blockIdx.y * 128;
    const int tx = tid & 15;
    const int ty = tid >> 4;

    int abase[2];
#pragma unroll
    for (int i = 0; i < 2; i++) {
        int lin = tid + 256 * i;
        int row = lin >> 2;
        int gm  = m0 + row;
        int base = -1;
        if (gm < MROWS) {
            int wdw = gm / NTOK, t = gm - wdw * NTOK;
            int b  = wdw / 25,  wi = wdw - b * 25;
            int wh = wi / 5,    ww = wi - wh * 5;
            int th = t / WS_,   tw = t - th * WS_;
            int y  = wh * WS_ + th;
            int xc = ww * WS_ + tw;
            if (y < IMGHW && xc < IMGHW)
                base = ((b * IMGHW + y) * IMGHW + xc) * DIM_;
        }
        abase[i] = base;
    }

    unsigned long long acc[8][4];
#pragma unroll
    for (int i = 0; i < 8; i++)
#pragma unroll
        for (int j = 0; j < 4; j++) acc[i][j] = 0ULL;

    float4 pa[2], pb[2];
#pragma unroll
    for (int i = 0; i < 2; i++) {
        int lin = tid + 256 * i;
        int kq  = (lin & 3) * 4;
        pa[i] = make_float4(0.f, 0.f, 0.f, 0.f);
        if (abase[i] >= 0) pa[i] = *(const float4*)(x + abase[i] + kq);
        int row = lin >> 2;
        pb[i] = *(const float4*)(w + (n0 + row) * DIM_ + kq);
    }
#pragma unroll
    for (int i = 0; i < 2; i++) {
        int lin = tid + 256 * i;
        int row = lin >> 2;
        int kq  = (lin & 3) * 4;
        As[0][kq + 0][row] = pa[i].x; As[0][kq + 1][row] = pa[i].y;
        As[0][kq + 2][row] = pa[i].z; As[0][kq + 3][row] = pa[i].w;
        Bs[0][kq + 0][row] = pb[i].x; Bs[0][kq + 1][row] = pb[i].y;
        Bs[0][kq + 2][row] = pb[i].z; Bs[0][kq + 3][row] = pb[i].w;
    }
    __syncthreads();

    const int NK = DIM_ / 16;
    for (int c = 0; c < NK; c++) {
        if (c + 1 < NK) {
            int k0 = (c + 1) * 16;
#pragma unroll
            for (int i = 0; i < 2; i++) {
                int lin = tid + 256 * i;
                int kq  = (lin & 3) * 4;
                pa[i] = make_float4(0.f, 0.f, 0.f, 0.f);
                if (abase[i] >= 0) pa[i] = *(const float4*)(x + abase[i] + k0 + kq);
                int row = lin >> 2;
                pb[i] = *(const float4*)(w + (n0 + row) * DIM_ + k0 + kq);
            }
        }
        const int buf = c & 1;
#pragma unroll
        for (int kk = 0; kk < 16; kk++) {
            float4 t0 = *(const float4*)&As[buf][kk][ty * 8];
            float4 t1 = *(const float4*)&As[buf][kk][ty * 8 + 4];
            float4 u0 = *(const float4*)&Bs[buf][kk][tx * 8];
            float4 u1 = *(const float4*)&Bs[buf][kk][tx * 8 + 4];
            unsigned long long a2[8], b2[4];
            a2[0]=pk2(t0.x,t0.x); a2[1]=pk2(t0.y,t0.y);
            a2[2]=pk2(t0.z,t0.z); a2[3]=pk2(t0.w,t0.w);
            a2[4]=pk2(t1.x,t1.x); a2[5]=pk2(t1.y,t1.y);
            a2[6]=pk2(t1.z,t1.z); a2[7]=pk2(t1.w,t1.w);
            b2[0]=pk2(u0.x,u0.y); b2[1]=pk2(u0.z,u0.w);
            b2[2]=pk2(u1.x,u1.y); b2[3]=pk2(u1.z,u1.w);
#pragma unroll
            for (int i = 0; i < 8; i++)
#pragma unroll
                for (int j = 0; j < 4; j++)
                    FFMA2(acc[i][j], a2[i], b2[j]);
        }
        if (c + 1 < NK) {
            const int nb = (c + 1) & 1;
#pragma unroll
            for (int i = 0; i < 2; i++) {
                int lin = tid + 256 * i;
                int row = lin >> 2;
                int kq  = (lin & 3) * 4;
                As[nb][kq + 0][row] = pa[i].x; As[nb][kq + 1][row] = pa[i].y;
                As[nb][kq + 2][row] = pa[i].z; As[nb][kq + 3][row] = pa[i].w;
                Bs[nb][kq + 0][row] = pb[i].x; Bs[nb][kq + 1][row] = pb[i].y;
                Bs[nb][kq + 2][row] = pb[i].z; Bs[nb][kq + 3][row] = pb[i].w;
            }
        }
        __syncthreads();
    }

#pragma unroll
    for (int i = 0; i < 8; i++) {
        int gm = m0 + ty * 8 + i;
        if (gm >= MROWS) continue;
        int wdw = gm / NTOK, t = gm - wdw * NTOK;
#pragma unroll
        for (int jp = 0; jp < 4; jp++) {
            float v0, v1;
            upk2(acc[i][jp], v0, v1);
#pragma unroll
            for (int e = 0; e < 2; e++) {
                int gn = n0 + tx * 8 + jp * 2 + e;
                float cv = (e ? v1 : v0) + bias[gn];
                int which = gn / DIM_;
                int r = gn - which * DIM_;
                int h = r >> 6, d = r & 63;
                int idx = ((wdw * NH_ + h) * NTOK + t) * HD_ + d;
                float* dst = (which == 0) ? g_q : ((which == 1) ? g_k : g_v);
                dst[idx] = cv;
            }
        }
    }
}

// =====================================================================
// scores v3.1: rel-as-GEMM + K1-prefetch overlap
// =====================================================================
#define SC_SMEM_FLOATS (8448 + 7424 + 8448)
#define SC_SMEM_BYTES  (SC_SMEM_FLOATS * 4)
#define NREL 27

__global__ __launch_bounds__(256)
void scores_gemm(const float* __restrict__ rph, const float* __restrict__ rpw)
{
    extern __shared__ float sm[];
    float* As  = sm;
    float* Th  = As + 8448;
    float* Tw  = Th + 3712;
    float* Bs  = Tw + 3712;
    float* tbl = Bs;

    const int tid = threadIdx.x;
    const int bh  = blockIdx.y;
    const int m0  = blockIdx.x * 128;
    const int tx  = tid & 15;
    const int ty  = tid >> 4;
    const float* Q = g_q + bh * (NTOK * HD_);
    const float* K = g_k + bh * (NTOK * HD_);

#pragma unroll
    for (int i = 0; i < 8; i++) {
        int e = tid + 256 * i;
        int row = e >> 4;
        int d0  = (e & 15) * 4;
        float4 v = make_float4(0.f, 0.f, 0.f, 0.f);
        if (m0 + row < NTOK) v = *(const float4*)(Q + (m0 + row) * HD_ + d0);
        As[(d0 + 0) * 132 + row] = v.x;
        As[(d0 + 1) * 132 + row] = v.y;
        As[(d0 + 2) * 132 + row] = v.z;
        As[(d0 + 3) * 132 + row] = v.w;
    }
    for (int i = tid; i < 2 * NREL * HD_; i += 256) {
        int isW = (i >= NREL * HD_);
        int l = isW ? i - NREL * HD_ : i;
        int r = l >> 6, d = l & 63;
        tbl[(isW ? 1755 : 0) + r * 65 + d] = __ldg((isW ? rpw : rph) + r * HD_ + d);
    }
    __syncthreads();

    // ---- prefetch K half-1 into regs (latency hidden by T GEMM below) ----
    float4 kpf[8];
#pragma unroll
    for (int i = 0; i < 8; i++) {
        int e = tid + 256 * i;
        int row = e >> 4;
        int d0  = (e & 15) * 4;
        kpf[i] = make_float4(0.f, 0.f, 0.f, 0.f);
        if (row < NTOK) kpf[i] = *(const float4*)(K + row * HD_ + d0);
    }

    // ---- Th/Tw = Q_tile @ table^T ----
    {
        const int ty2 = tid >> 3;
        const int tx2 = tid & 7;
#pragma unroll
        for (int tb = 0; tb < 2; tb++) {
            const float* tb_base = tbl + (tb ? 1755 : 0);
            float* Tout = tb ? Tw : Th;
            float t[4][4];
#pragma unroll
            for (int i = 0; i < 4; i++)
#pragma unroll
                for (int j = 0; j < 4; j++) t[i][j] = 0.f;
#pragma unroll 8
            for (int d = 0; d < HD_; d++) {
                float qv[4], tv[4];
#pragma unroll
                for (int i = 0; i < 4; i++)
                    qv[i] = As[d * 132 + ty2 * 4 + i];
#pragma unroll
                for (int j = 0; j < 4; j++) {
                    int col = tx2 * 4 + j;
                    tv[j] = tb_base[(col < NREL ? col : 0) * 65 + d];
                }
#pragma unroll
                for (int i = 0; i < 4; i++)
#pragma unroll
                    for (int j = 0; j < 4; j++)
                        t[i][j] = fmaf(qv[i], tv[j], t[i][j]);
            }
#pragma unroll
            for (int j = 0; j < 4; j++) {
                int col = tx2 * 4 + j;
                if (col < NREL) {
#pragma unroll
                    for (int i = 0; i < 4; i++)
                        Tout[(ty2 * 4 + i) * 29 + col] = t[i][j];
                }
            }
        }
    }
    __syncthreads();   // all T reads of tbl done; Bs region free

    for (int half = 0; half < 2; half++) {
        const int n0 = half * 128;
        if (half == 0) {
            // store prefetched K1
#pragma unroll
            for (int i = 0; i < 8; i++) {
                int e = tid + 256 * i;
                int row = e >> 4;
                int d0  = (e & 15) * 4;
                Bs[(d0 + 0) * 132 + row] = kpf[i].x;
                Bs[(d0 + 1) * 132 + row] = kpf[i].y;
                Bs[(d0 + 2) * 132 + row] = kpf[i].z;
                Bs[(d0 + 3) * 132 + row] = kpf[i].w;
            }
        } else {
#pragma unroll
            for (int i = 0; i < 8; i++) {
                int e = tid + 256 * i;
                int row = e >> 4;
                int d0  = (e & 15) * 4;
                float4 v = make_float4(0.f, 0.f, 0.f, 0.f);
                if (n0 + row < NTOK) v = *(const float4*)(K + (n0 + row) * HD_ + d0);
                Bs[(d0 + 0) * 132 + row] = v.x;
                Bs[(d0 + 1) * 132 + row] = v.y;
                Bs[(d0 + 2) * 132 + row] = v.z;
                Bs[(d0 + 3) * 132 + row] = v.w;
            }
        }
        __syncthreads();

        float acc[8][8];
#pragma unroll
        for (int i = 0; i < 8; i++)
#pragma unroll
            for (int j = 0; j < 8; j++) acc[i][j] = 0.f;

#pragma unroll 8
        for (int kk = 0; kk < HD_; kk++) {
            float a[8], b[8];
            float4 t0 = *(const float4*)&As[kk * 132 + ty * 8];
            float4 t1 = *(const float4*)&As[kk * 132 + ty * 8 + 4];
            a[0]=t0.x; a[1]=t0.y; a[2]=t0.z; a[3]=t0.w;
            a[4]=t1.x; a[5]=t1.y; a[6]=t1.z; a[7]=t1.w;
            float4 u0 = *(const float4*)&Bs[kk * 132 + tx * 8];
            float4 u1 = *(const float4*)&Bs[kk * 132 + tx * 8 + 4];
            b[0]=u0.x; b[1]=u0.y; b[2]=u0.z; b[3]=u0.w;
            b[4]=u1.x; b[5]=u1.y; b[6]=u1.z; b[7]=u1.w;
#pragma unroll
            for (int i = 0; i < 8; i++)
#pragma unroll
                for (int j = 0; j < 8; j++)
                    acc[i][j] = fmaf(a[i], b[j], acc[i][j]);
        }

        int khs[8], kws[8];
#pragma unroll
        for (int j = 0; j < 8; j++) {
            int gn = n0 + tx * 8 + j;
            int kh = gn / WS_;
            khs[j] = kh;
            kws[j] = gn - kh * WS_;
        }
#pragma unroll
        for (int i = 0; i < 8; i++) {
            int gm = m0 + ty * 8 + i;
            if (gm >= NTOK) continue;
            int lrow = ty * 8 + i;
            int qh  = gm / WS_;
            int qwc = gm - qh * WS_;
            float* srow = g_s + (size_t)bh * NN_ + gm * NTOK;
            const float* thr = Th + lrow * 29 + (qh + WS_ - 1);
            const float* twr = Tw + lrow * 29 + (qwc + WS_ - 1);
#pragma unroll
            for (int j = 0; j < 8; j++) {
                int gn = n0 + tx * 8 + j;
                if (gn >= NTOK) continue;
                srow[gn] = acc[i][j] * 0.125f + thr[-khs[j]] + twr[-kws[j]];
            }
        }
        __syncthreads();
    }
}

// =====================================================================
// softmax (passing version)
// =====================================================================
__global__ __launch_bounds__(128)
void softmax_kernel()
{
    const int lane = threadIdx.x & 31;
    const size_t row = (size_t)blockIdx.x * 4 + (threadIdx.x >> 5);
    float* s = g_s + row * NTOK;

    float v[7];
    float mx = -INFINITY;
#pragma unroll
    for (int t = 0; t < 7; t++) {
        int j = lane + 32 * t;
        v[t] = (j < NTOK) ? s[j] : -INFINITY;
        mx = fmaxf(mx, v[t]);
    }
#pragma unroll
    for (int off = 16; off > 0; off >>= 1)
        mx = fmaxf(mx, __shfl_xor_sync(0xffffffffu, mx, off));
    float sum = 0.f;
#pragma unroll
    for (int t = 0; t < 7; t++) {
        int j = lane + 32 * t;
        if (j < NTOK) {
            float e = __expf(v[t] - mx);
            v[t] = e;
            sum += e;
        }
    }
#pragma unroll
    for (int off = 16; off > 0; off >>= 1)
        sum += __shfl_xor_sync(0xffffffffu, sum, off);
    float inv = 1.f / sum;
#pragma unroll
    for (int t = 0; t < 7; t++) {
        int j = lane + 32 * t;
        if (j < NTOK) s[j] = v[t] * inv;
    }
}

// =====================================================================
// av v2 (passing round-14/15 version)
// =====================================================================
#define AV_SMEM_FLOATS (208 * 68 + 2 * 16 * 260)
#define AV_SMEM_BYTES  (AV_SMEM_FLOATS * 4)

__global__ __launch_bounds__(256)
void av_gemm()
{
    extern __shared__ float sm[];
    float* Vs = sm;
    float* Ab = Vs + 208 * 68;

    const int tid = threadIdx.x;
    const int bh  = blockIdx.x;
    const int tx  = tid & 7;
    const int ty  = tid >> 3;
    const float* P = g_s + (size_t)bh * NN_;
    const float* V = g_v + bh * (NTOK * HD_);
    const int wdw = bh / NH_, hh = bh - wdw * NH_;

    for (int i = tid; i < 208 * 16; i += 256) {
        int row = i >> 4;
        int c4  = (i & 15) * 4;
        float4 v = make_float4(0.f, 0.f, 0.f, 0.f);
        if (row < NTOK) v = *(const float4*)(V + row * HD_ + c4);
        *(float4*)&Vs[row * 68 + c4] = v;
    }

    float acc[8][8];
#pragma unroll
    for (int i = 0; i < 8; i++)
#pragma unroll
        for (int j = 0; j < 8; j++) acc[i][j] = 0.f;

    const int NC = 13;
    float4 pa[4];

#pragma unroll
    for (int i = 0; i < 4; i++) {
        int lin = tid + 256 * i;
        int row = lin >> 2;
        int kq  = (lin & 3) * 4;
        pa[i] = make_float4(0.f, 0.f, 0.f, 0.f);
        if (row < NTOK) pa[i] = *(const float4*)(P + row * NTOK + kq);
    }
#pragma unroll
    for (int i = 0; i < 4; i++) {
        int lin = tid + 256 * i;
        int row = lin >> 2;
        int kq  = (lin & 3) * 4;
        Ab[(kq + 0) * 260 + row] = pa[i].x;
        Ab[(kq + 1) * 260 + row] = pa[i].y;
        Ab[(kq + 2) * 260 + row] = pa[i].z;
        Ab[(kq + 3) * 260 + row] = pa[i].w;
    }
    __syncthreads();

    for (int c = 0; c < NC; c++) {
        if (c + 1 < NC) {
            int k0 = (c + 1) * 16;
#pragma unroll
            for (int i = 0; i < 4; i++) {
                int lin = tid + 256 * i;
                int row = lin >> 2;
                int kq  = (lin & 3) * 4;
                pa[i] = make_float4(0.f, 0.f, 0.f, 0.f);
                if (row < NTOK && (k0 + kq) < NTOK)
                    pa[i] = *(const float4*)(P + row * NTOK + k0 + kq);
            }
        }
        const float* Ac = Ab + (c & 1) * 4160;
        const float* Vc = Vs + c * 16 * 68;
#pragma unroll
        for (int kk = 0; kk < 16; kk++) {
            float a[8], b[8];
            float4 t0 = *(const float4*)&Ac[kk * 260 + ty * 8];
            float4 t1 = *(const float4*)&Ac[kk * 260 + ty * 8 + 4];
            a[0]=t0.x; a[1]=t0.y; a[2]=t0.z; a[3]=t0.w;
            a[4]=t1.x; a[5]=t1.y; a[6]=t1.z; a[7]=t1.w;
            float4 u0 = *(const float4*)&Vc[kk * 68 + tx * 8];
            float4 u1 = *(const float4*)&Vc[kk * 68 + tx * 8 + 4];
            b[0]=u0.x; b[1]=u0.y; b[2]=u0.z; b[3]=u0.w;
            b[4]=u1.x; b[5]=u1.y; b[6]=u1.z; b[7]=u1.w;
#pragma unroll
            for (int i = 0; i < 8; i++)
#pragma unroll
                for (int j = 0; j < 8; j++)
                    acc[i][j] = fmaf(a[i], b[j], acc[i][j]);
        }
        if (c + 1 < NC) {
            float* An = Ab + ((c + 1) & 1) * 4160;
#pragma unroll
            for (int i = 0; i < 4; i++) {
                int lin = tid + 256 * i;
                int row = lin >> 2;
                int kq  = (lin & 3) * 4;
                An[(kq + 0) * 260 + row] = pa[i].x;
                An[(kq + 1) * 260 + row] = pa[i].y;
                An[(kq + 2) * 260 + row] = pa[i].z;
                An[(kq + 3) * 260 + row] = pa[i].w;
            }
        }
        __syncthreads();
    }

#pragma unroll
    for (int i = 0; i < 8; i++) {
        int gm = ty * 8 + i;
        if (gm >= NTOK) continue;
        float* orow = g_ao + (size_t)(wdw * NTOK + gm) * DIM_ + hh * HD_ + tx * 8;
        *(float4*)orow       = make_float4(acc[i][0], acc[i][1], acc[i][2], acc[i][3]);
        *(float4*)(orow + 4) = make_float4(acc[i][4], acc[i][5], acc[i][6], acc[i][7]);
    }
}

// =====================================================================
// GEMM 2: proj (round-15 passing version, f32x2)
// =====================================================================
__global__ __launch_bounds__(256)
void proj_gemm(const float* __restrict__ w, const float* __restrict__ bias,
               float* __restrict__ out)
{
    __shared__ float As[2][16][132];
    __shared__ float Bs[2][16][132];
    const int tid = threadIdx.x;
    const int m0 = blockIdx.x * 128;
    const int n0 = blockIdx.y * 128;
    const int tx = tid & 15;
    const int ty = tid >> 4;

    int abase[2];
#pragma unroll
    for (int i = 0; i < 2; i++) {
        int lin = tid + 256 * i;
        int row = lin >> 2;
        int gm  = m0 + row;
        abase[i] = (gm < MROWS) ? gm * DIM_ : -1;
    }

    unsigned long long acc[8][4];
#pragma unroll
    for (int i = 0; i < 8; i++)
#pragma unroll
        for (int j = 0; j < 4; j++) acc[i][j] = 0ULL;

    float4 pa[2], pb[2];
#pragma unroll
    for (int i = 0; i < 2; i++) {
        int lin = tid + 256 * i;
        int kq  = (lin & 3) * 4;
        pa[i] = make_float4(0.f, 0.f, 0.f, 0.f);
        if (abase[i] >= 0) pa[i] = *(const float4*)(g_ao + abase[i] + kq);
        int row = lin >> 2;
        pb[i] = *(const float4*)(w + (n0 + row) * DIM_ + kq);
    }
#pragma unroll
    for (int i = 0; i < 2; i++) {
        int lin = tid + 256 * i;
        int row = lin >> 2;
        int kq  = (lin & 3) * 4;
        As[0][kq + 0][row] = pa[i].x; As[0][kq + 1][row] = pa[i].y;
        As[0][kq + 2][row] = pa[i].z; As[0][kq + 3][row] = pa[i].w;
        Bs[0][kq + 0][row] = pb[i].x; Bs[0][kq + 1][row] = pb[i].y;
        Bs[0][kq + 2][row] = pb[i].z; Bs[0][kq + 3][row] = pb[i].w;
    }
    __syncthreads();

    const int NK = DIM_ / 16;
    for (int c = 0; c < NK; c++) {
        if (c + 1 < NK) {
            int k0 = (c + 1) * 16;
#pragma unroll
            for (int i = 0; i < 2; i++) {
                int lin = tid + 256 * i;
                int kq  = (lin & 3) * 4;
                pa[i] = make_float4(0.f, 0.f, 0.f, 0.f);
                if (abase[i] >= 0) pa[i] = *(const float4*)(g_ao + abase[i] + k0 + kq);
                int row = lin >> 2;
                pb[i] = *(const float4*)(w + (n0 + row) * DIM_ + k0 + kq);
            }
        }
        const int buf = c & 1;
#pragma unroll
        for (int kk = 0; kk < 16; kk++) {
            float4 t0 = *(const float4*)&As[buf][kk][ty * 8];
            float4 t1 = *(const float4*)&As[buf][kk][ty * 8 + 4];
            float4 u0 = *(const float4*)&Bs[buf][kk][tx * 8];
            float4 u1 = *(const float4*)&Bs[buf][kk][tx * 8 + 4];
            unsigned long long a2[8], b2[4];
            a2[0]=pk2(t0.x,t0.x); a2[1]=pk2(t0.y,t0.y);
            a2[2]=pk2(t0.z,t0.z); a2[3]=pk2(t0.w,t0.w);
            a2[4]=pk2(t1.x,t1.x); a2[5]=pk2(t1.y,t1.y);
            a2[6]=pk2(t1.z,t1.z); a2[7]=pk2(t1.w,t1.w);
            b2[0]=pk2(u0.x,u0.y); b2[1]=pk2(u0.z,u0.w);
            b2[2]=pk2(u1.x,u1.y); b2[3]=pk2(u1.z,u1.w);
#pragma unroll
            for (int i = 0; i < 8; i++)
#pragma unroll
                for (int j = 0; j < 4; j++)
                    FFMA2(acc[i][j], a2[i], b2[j]);
        }
        if (c + 1 < NK) {
            const int nb = (c + 1) & 1;
#pragma unroll
            for (int i = 0; i < 2; i++) {
                int lin = tid + 256 * i;
                int row = lin >> 2;
                int kq  = (lin & 3) * 4;
                As[nb][kq + 0][row] = pa[i].x; As[nb][kq + 1][row] = pa[i].y;
                As[nb][kq + 2][row] = pa[i].z; As[nb][kq + 3][row] = pa[i].w;
                Bs[nb][kq + 0][row] = pb[i].x; Bs[nb][kq + 1][row] = pb[i].y;
                Bs[nb][kq + 2][row] = pb[i].z; Bs[nb][kq + 3][row] = pb[i].w;
            }
        }
        __syncthreads();
    }

#pragma unroll
    for (int i = 0; i < 8; i++) {
        int gm = m0 + ty * 8 + i;
        if (gm >= MROWS) continue;
        int wdw = gm / NTOK, t = gm - wdw * NTOK;
        int b  = wdw / 25,  wi = wdw - b * 25;
        int wh = wi / 5,    ww = wi - wh * 5;
        int th = t / WS_,   tw = t - th * WS_;
        int y  = wh * WS_ + th;
        int xc = ww * WS_ + tw;
        if (y >= IMGHW || xc >= IMGHW) continue;
        float* orow = out + ((b * IMGHW + y) * IMGHW + xc) * DIM_;
#pragma unroll
        for (int jp = 0; jp < 4; jp++) {
            float v0, v1;
            upk2(acc[i][jp], v0, v1);
            int gn = n0 + tx * 8 + jp * 2;
            orow[gn]     = v0 + bias[gn];
            orow[gn + 1] = v1 + bias[gn + 1];
        }
    }
}

// =====================================================================
extern "C" void kernel_launch(void* const* d_in, const int* in_sizes, int n_in,
                              void* d_out, int out_size)
{
    const float* x      = (const float*)d_in[0];
    const float* qkv_w  = (const float*)d_in[1];
    const float* qkv_b  = (const float*)d_in[2];
    const float* proj_w = (const float*)d_in[3];
    const float* proj_b = (const float*)d_in[4];
    const float* rph    = (const float*)d_in[5];
    const float* rpw    = (const float*)d_in[6];
    float* out = (float*)d_out;

    cudaFuncSetAttribute(scores_gemm,
                         cudaFuncAttributeMaxDynamicSharedMemorySize, SC_SMEM_BYTES);
    cudaFuncSetAttribute(av_gemm,
                         cudaFuncAttributeMaxDynamicSharedMemorySize, AV_SMEM_BYTES);

    dim3 g1((MROWS + 127) / 128, QKV_N / 128);
    qkv_gemm<<<g1, 256>>>(x, qkv_w, qkv_b);

    dim3 gs(2, BH_);
    scores_gemm<<<gs, 256, SC_SMEM_BYTES>>>(rph, rpw);

    softmax_kernel<<<(BH_ * NTOK) / 4, 128>>>();

    av_gemm<<<BH_, 256, AV_SMEM_BYTES>>>();

    dim3 g2((MROWS + 127) / 128, DIM_ / 128);
    proj_gemm<<<g2, 256>>>(proj_w, proj_b, out);
}